// round 13
// baseline (speedup 1.0000x reference)
#include <cuda_runtime.h>
#include <cuda_bf16.h>
#include <cstdint>

#define EPS_ 1e-3f
#define LOG2E 1.4426950408889634f
#define B_   2
#define H_   96
#define W_   96
#define C_   64
#define CQ   8
#define HW_  9216
#define BHW  (B_*HW_)
#define NMT  72            // number of 128-wide n-chunks
#define NH_  2             // n-halves in fused
#define NCH  (NMT / NH_)   // chunks per fused CTA
#define MZ_  8             // m-splits in stats
#define MCH  (NMT / MZ_)   // chunks of 128 m per stats block

// ---------------- scratch (static device arrays; no allocation) ----------------
__device__ unsigned       g_q[BHW * CQ];                // Q' = tf32(q * log2e) bits [n][8]
__device__ unsigned       g_k[BHW * CQ];                // K  = tf32(k) bits [m][8]
__device__ float          g_v[BHW * C_];                // V rows, fp32 [n][c]
__device__ __nv_bfloat16  g_vsT[(size_t)B_ * C_ * HW_]; // Vs^T [b][c][n], bf16
__device__ float          g_part[B_ * MZ_ * HW_];       // stats partials [b][mz][n]
__device__ float          g_pd[(size_t)NH_ * BHW * C_]; // fused partial D [nh][b*HW+m][c]

// ---------------- helpers ----------------
__device__ __forceinline__ unsigned f2tf32(float f) {
    unsigned r;
    asm("cvt.rna.tf32.f32 %0, %1;" : "=r"(r) : "f"(f));
    return r;
}
__device__ __forceinline__ float ex2(float x) {
    float r;
    asm("ex2.approx.f32 %0, %1;" : "=f"(r) : "f"(x));
    return r;
}
__device__ __forceinline__ unsigned packbf2(float hi, float lo) {
    unsigned r;
    asm("cvt.rn.bf16x2.f32 %0, %1, %2;" : "=r"(r) : "f"(hi), "f"(lo));
    return r;
}
__device__ __forceinline__ void mma_tf32(float* d, const unsigned* a, unsigned b0, unsigned b1) {
    asm volatile(
        "mma.sync.aligned.m16n8k8.row.col.f32.tf32.tf32.f32 "
        "{%0,%1,%2,%3}, {%4,%5,%6,%7}, {%8,%9}, {%0,%1,%2,%3};\n"
        : "+f"(d[0]), "+f"(d[1]), "+f"(d[2]), "+f"(d[3])
        : "r"(a[0]), "r"(a[1]), "r"(a[2]), "r"(a[3]), "r"(b0), "r"(b1));
}
__device__ __forceinline__ void mma_bf16(float* d, const unsigned* a, unsigned b0, unsigned b1) {
    asm volatile(
        "mma.sync.aligned.m16n8k16.row.col.f32.bf16.bf16.f32 "
        "{%0,%1,%2,%3}, {%4,%5,%6,%7}, {%8,%9}, {%0,%1,%2,%3};\n"
        : "+f"(d[0]), "+f"(d[1]), "+f"(d[2]), "+f"(d[3])
        : "r"(a[0]), "r"(a[1]), "r"(a[2]), "r"(a[3]), "r"(b0), "r"(b1));
}
__device__ __forceinline__ void ldsm4(unsigned* r, const void* p) {
    unsigned a = (unsigned)__cvta_generic_to_shared(p);
    asm volatile("ldmatrix.sync.aligned.m8n8.x4.shared.b16 {%0,%1,%2,%3}, [%4];"
                 : "=r"(r[0]), "=r"(r[1]), "=r"(r[2]), "=r"(r[3]) : "r"(a));
}
__device__ __forceinline__ void cpa16(void* dst, const void* src) {
    unsigned d = (unsigned)__cvta_generic_to_shared(dst);
    asm volatile("cp.async.cg.shared.global [%0], [%1], 16;" :: "r"(d), "l"(src));
}
__device__ __forceinline__ void cpa_commit() { asm volatile("cp.async.commit_group;"); }
template <int N>
__device__ __forceinline__ void cpa_wait() { asm volatile("cp.async.wait_group %0;" :: "n"(N)); }

// ---------------- kernel 1: fused convs + BN + ReLU (4 pixels / block) ----------------
__global__ __launch_bounds__(256) void prep_kernel(const float* __restrict__ x,
    const float* __restrict__ Wq, const float* __restrict__ bq,
    const float* __restrict__ gq, const float* __restrict__ betaq,
    const float* __restrict__ mq, const float* __restrict__ vq,
    const float* __restrict__ Wk, const float* __restrict__ bk,
    const float* __restrict__ gk, const float* __restrict__ betak,
    const float* __restrict__ mk, const float* __restrict__ vk,
    const float* __restrict__ Wv, const float* __restrict__ bv)
{
    __shared__ float xc[6][C_];
    __shared__ float xu[4][C_];
    __shared__ float xd[4][C_];
    int pix0 = blockIdx.x * 4;
    int b = pix0 / HW_;
    int n0 = pix0 - b * HW_;
    int h = n0 / W_, w0 = n0 - h * W_;
    int t = threadIdx.x;
    const float* xb = x + (size_t)b * HW_ * C_;

    for (int i = t; i < 6 * C_; i += 256) {
        int j = i >> 6, c = i & 63, wi = w0 - 1 + j;
        xc[j][c] = (wi >= 0 && wi < W_) ? xb[(h * W_ + wi) * C_ + c] : 0.f;
    }
    for (int i = t; i < 4 * C_; i += 256) {
        int j = i >> 6, c = i & 63;
        xu[j][c] = (h > 0)      ? xb[((h - 1) * W_ + w0 + j) * C_ + c] : 0.f;
        xd[j][c] = (h < H_ - 1) ? xb[((h + 1) * W_ + w0 + j) * C_ + c] : 0.f;
    }
    __syncthreads();

    int px = t >> 6, c = t & 63;
    int pix = pix0 + px;

    float acc = bv[c];
    #pragma unroll 8
    for (int ci = 0; ci < C_; ci++)
        acc = fmaf(xc[px + 1][ci], Wv[ci * C_ + c], acc);
    g_v[(size_t)pix * C_ + c] = acc;

    if (c < CQ) {
        float s = 0.f;
        #pragma unroll 8
        for (int ci = 0; ci < C_; ci++) {
            s = fmaf(xc[px    ][ci], Wq[(0 * C_ + ci) * CQ + c], s);
            s = fmaf(xc[px + 1][ci], Wq[(1 * C_ + ci) * CQ + c], s);
            s = fmaf(xc[px + 2][ci], Wq[(2 * C_ + ci) * CQ + c], s);
        }
        float sc  = gq[c] * rsqrtf(vq[c] + EPS_);
        float val = fmaf(s + bq[c] - mq[c], sc, betaq[c]);
        g_q[pix * CQ + c] = f2tf32(fmaxf(val, 0.f) * LOG2E);
    } else if (c < 2 * CQ) {
        int cc = c - CQ;
        float s = 0.f;
        #pragma unroll 8
        for (int ci = 0; ci < C_; ci++) {
            s = fmaf(xu[px    ][ci], Wk[(0 * C_ + ci) * CQ + cc], s);
            s = fmaf(xc[px + 1][ci], Wk[(1 * C_ + ci) * CQ + cc], s);
            s = fmaf(xd[px    ][ci], Wk[(2 * C_ + ci) * CQ + cc], s);
        }
        float sc  = gk[cc] * rsqrtf(vk[cc] + EPS_);
        float val = fmaf(s + bk[cc] - mk[cc], sc, betak[cc]);
        g_k[pix * CQ + cc] = f2tf32(fmaxf(val, 0.f));
    }
}

// ---------------- kernel 2: softmax-denominator partials ----------------
__global__ __launch_bounds__(256) void stats_kernel()
{
    __shared__ unsigned ks[2][128][12];
    int b  = blockIdx.y;
    int n0 = blockIdx.x * 128;
    int mz = blockIdx.z;
    int m_base = mz * (HW_ / MZ_);
    int t = threadIdx.x, lane = t & 31, w = t >> 5;
    int g = lane >> 2, tq = lane & 3;
    size_t bHW = (size_t)b * HW_;
    const unsigned* kb = &g_k[bHW * 8];

    unsigned bq[4];
    {
        const unsigned* qp = &g_q[(bHW + n0 + 16 * w + g) * 8];
        bq[0] = qp[tq];
        bq[1] = qp[tq + 4];
        bq[2] = qp[64 + tq];
        bq[3] = qp[64 + tq + 4];
    }

    {
        int row = t >> 1, seg = t & 1;
        cpa16(&ks[0][row][seg * 4], kb + (m_base + row) * 8 + seg * 4);
        cpa_commit();
    }

    float cs0 = 0.f, cs1 = 0.f, cs2 = 0.f, cs3 = 0.f;

    for (int ch = 0; ch < MCH; ch++) {
        int buf = ch & 1;
        if (ch + 1 < MCH) {
            int row = t >> 1, seg = t & 1;
            cpa16(&ks[buf ^ 1][row][seg * 4], kb + (m_base + (ch + 1) * 128 + row) * 8 + seg * 4);
            cpa_commit();
            cpa_wait<1>();
        } else {
            cpa_wait<0>();
        }
        __syncthreads();

        #pragma unroll
        for (int i = 0; i < 8; i++) {
            unsigned a[4];
            a[0] = ks[buf][16 * i + g    ][tq    ];
            a[1] = ks[buf][16 * i + g + 8][tq    ];
            a[2] = ks[buf][16 * i + g    ][tq + 4];
            a[3] = ks[buf][16 * i + g + 8][tq + 4];
            float d[4] = {0.f, 0.f, 0.f, 0.f};
            float e[4] = {0.f, 0.f, 0.f, 0.f};
            mma_tf32(d, a, bq[0], bq[1]);
            mma_tf32(e, a, bq[2], bq[3]);
            cs0 += ex2(d[0]) + ex2(d[2]);
            cs1 += ex2(d[1]) + ex2(d[3]);
            cs2 += ex2(e[0]) + ex2(e[2]);
            cs3 += ex2(e[1]) + ex2(e[3]);
        }
        __syncthreads();
    }

    #pragma unroll
    for (int s = 16; s >= 4; s >>= 1) {
        cs0 += __shfl_xor_sync(0xffffffffu, cs0, s);
        cs1 += __shfl_xor_sync(0xffffffffu, cs1, s);
        cs2 += __shfl_xor_sync(0xffffffffu, cs2, s);
        cs3 += __shfl_xor_sync(0xffffffffu, cs3, s);
    }
    if (lane < 4) {
        float* rp = &g_part[((b * MZ_) + mz) * HW_ + n0 + 16 * w];
        rp[2 * tq]     = cs0;
        rp[2 * tq + 1] = cs1;
        rp[2 * tq + 8] = cs2;
        rp[2 * tq + 9] = cs3;
    }
}

// ---------------- kernel 3: Vs^T = bf16(gamma * v / rowsum), rowsum reduced inline ----------------
__global__ void scalev_kernel(const float* __restrict__ gamma)
{
    size_t o = (size_t)blockIdx.x * 256 + threadIdx.x;  // over B*C*HW, n fastest
    int n = (int)(o % HW_);
    int c = (int)((o / HW_) % C_);
    int b = (int)(o / ((size_t)HW_ * C_));
    float s = 0.f;
    #pragma unroll
    for (int mz = 0; mz < MZ_; mz++)
        s += g_part[((b * MZ_) + mz) * HW_ + n];
    float val = g_v[((size_t)(b * HW_ + n)) * C_ + c] * gamma[0] / s;
    g_vsT[o] = __float2bfloat16(val);
}

// ---------------- kernel 4: fused P-in-registers GEMM -> partial D ----------------
// grid (144, B, NH_): CTA = 64m x 64c over one n-half (36 chunks). 128 threads,
// 4 warps: wm=w&1 (32 m), wc=w>>1 (32 c). acc=32 regs -> 4 CTAs/SM = 16 warps/SM.
#define VSOFF   0
#define VSBUF   17408                    // 64 rows x 136 bf16
#define QSOFF   (2 * VSBUF)              // 34816
#define QSBUF   4096                     // 128 rows x 8 words
#define FK_SMEM (QSOFF + 2 * QSBUF)      // 43008

__global__ __launch_bounds__(128, 4)
void fused_kernel(float* __restrict__ pd)
{
    extern __shared__ __align__(16) char smem[];
    __nv_bfloat16* VsB = (__nv_bfloat16*)(smem + VSOFF);
    unsigned*      QsB = (unsigned*)(smem + QSOFF);
#define VS(bf, r, c) VsB[(bf) * (64 * 136) + (r) * 136 + (c)]
#define QS(bf)       (QsB + (bf) * 1024)

    int b  = blockIdx.y;
    int nh = blockIdx.z;
    int m0 = blockIdx.x * 64;
    int nb0 = nh * NCH * 128;            // n-range base
    int t = threadIdx.x, lane = t & 31, w = t >> 5;     // 4 warps
    int g = lane >> 2, tq = lane & 3;
    int wm = w & 1;        // m half (32 rows)
    int wc = w >> 1;       // c half (32 cols)
    size_t bHW = (size_t)b * HW_;
    const unsigned* kb = &g_k[bHW * 8];
    const unsigned* qb = &g_q[(bHW + nb0) * 8];
    const __nv_bfloat16* Ag = &g_vsT[(size_t)b * C_ * HW_ + nb0];

    // K A-fragments for this warp's 32 m-rows (2 m-tiles, fixed all kernel)
    int mw = m0 + 32 * wm;
    unsigned ka[2][4];
    #pragma unroll
    for (int mt = 0; mt < 2; mt++) {
        ka[mt][0] = kb[(mw + 16 * mt + g    ) * 8 + tq    ];
        ka[mt][1] = kb[(mw + 16 * mt + g + 8) * 8 + tq    ];
        ka[mt][2] = kb[(mw + 16 * mt + g    ) * 8 + tq + 4];
        ka[mt][3] = kb[(mw + 16 * mt + g + 8) * 8 + tq + 4];
    }

    float acc[2][4][4];
    #pragma unroll
    for (int mt = 0; mt < 2; mt++)
        #pragma unroll
        for (int i = 0; i < 4; i++)
            #pragma unroll
            for (int j = 0; j < 4; j++) acc[mt][i][j] = 0.f;

    // prefetch chunk 0: Vs 1024 x 16B + Q 256 x 16B
    #pragma unroll
    for (int j = 0; j < 8; j++) {
        int idx = t + j * 128, row = idx >> 4, seg = idx & 15;
        cpa16(&VS(0, row, seg * 8), Ag + (size_t)row * HW_ + seg * 8);
    }
    #pragma unroll
    for (int j = 0; j < 2; j++) {
        int idx = t + j * 128, row = idx >> 1, seg = idx & 1;
        cpa16(QS(0) + row * 8 + seg * 4, qb + (size_t)row * 8 + seg * 4);
    }
    cpa_commit();
    cpa_wait<0>();
    __syncthreads();

    for (int ck = 0; ck < NCH; ck++) {
        int buf = ck & 1;
        bool more = (ck + 1 < NCH);
        if (more) {
            int n1 = (ck + 1) * 128;
            #pragma unroll
            for (int j = 0; j < 8; j++) {
                int idx = t + j * 128, row = idx >> 4, seg = idx & 15;
                cpa16(&VS(buf ^ 1, row, seg * 8), Ag + (size_t)row * HW_ + n1 + seg * 8);
            }
            #pragma unroll
            for (int j = 0; j < 2; j++) {
                int idx = t + j * 128, row = idx >> 1, seg = idx & 1;
                cpa16(QS(buf ^ 1) + row * 8 + seg * 4, qb + (size_t)(n1 + row) * 8 + seg * 4);
            }
            cpa_commit();
        }

        const unsigned* qs = QS(buf);
        #pragma unroll
        for (int s = 0; s < 8; s++) {
            int nb = 16 * s;
            unsigned q0 = qs[(nb + g    ) * 8 + tq    ];
            unsigned q1 = qs[(nb + g    ) * 8 + tq + 4];
            unsigned q2 = qs[(nb + 8 + g) * 8 + tq    ];
            unsigned q3 = qs[(nb + 8 + g) * 8 + tq + 4];
            unsigned a[2][4];
            #pragma unroll
            for (int mt = 0; mt < 2; mt++) {
                float d[4] = {0.f, 0.f, 0.f, 0.f};
                float e[4] = {0.f, 0.f, 0.f, 0.f};
                mma_tf32(d, ka[mt], q0, q1);
                mma_tf32(e, ka[mt], q2, q3);
                a[mt][0] = packbf2(ex2(d[1]), ex2(d[0]));
                a[mt][1] = packbf2(ex2(d[3]), ex2(d[2]));
                a[mt][2] = packbf2(ex2(e[1]), ex2(e[0]));
                a[mt][3] = packbf2(ex2(e[3]), ex2(e[2]));
            }
            #pragma unroll
            for (int cb = 0; cb < 2; cb++) {
                unsigned bb[4];
                ldsm4(bb, &VS(buf, 32 * wc + cb * 16 + (lane & 7) + ((lane >> 4) & 1) * 8,
                              nb + ((lane >> 3) & 1) * 8));
                #pragma unroll
                for (int mt = 0; mt < 2; mt++) {
                    mma_bf16(acc[mt][2 * cb    ], a[mt], bb[0], bb[1]);
                    mma_bf16(acc[mt][2 * cb + 1], a[mt], bb[2], bb[3]);
                }
            }
        }
        if (more) cpa_wait<0>();
        __syncthreads();
    }

    // write partial D for this n-half
    float* pdb = pd + ((size_t)nh * B_ + b) * HW_ * C_;
    #pragma unroll
    for (int mt = 0; mt < 2; mt++) {
        int m = m0 + 32 * wm + 16 * mt + g;
        #pragma unroll
        for (int j = 0; j < 4; j++) {
            int cc = 32 * wc + 16 * (j >> 1) + 8 * (j & 1) + 2 * tq;
            size_t i0 = (size_t)m * C_ + cc;
            float2 o0 = { acc[mt][j][0], acc[mt][j][1] };
            float2 o1 = { acc[mt][j][2], acc[mt][j][3] };
            *(float2*)&pdb[i0]          = o0;
            *(float2*)&pdb[i0 + 8 * C_] = o1;
        }
    }
#undef VS
#undef QS
}

// ---------------- kernel 5: combine partials + residual ----------------
__global__ void combine_kernel(const float* __restrict__ x, float* __restrict__ out)
{
    size_t i = ((size_t)blockIdx.x * 256 + threadIdx.x) * 4;   // over BHW*C_, float4
    float4 p0 = *(const float4*)&g_pd[i];
    float4 p1 = *(const float4*)&g_pd[(size_t)BHW * C_ + i];
    float4 xv = *(const float4*)&x[i];
    float4 o;
    o.x = p0.x + p1.x + xv.x;
    o.y = p0.y + p1.y + xv.y;
    o.z = p0.z + p1.z + xv.z;
    o.w = p0.w + p1.w + xv.w;
    *(float4*)&out[i] = o;
}

// ---------------- launch ----------------
extern "C" void kernel_launch(void* const* d_in, const int* in_sizes, int n_in,
                              void* d_out, int out_size)
{
    const float* x     = (const float*)d_in[0];
    const float* Wq    = (const float*)d_in[1];
    const float* bq    = (const float*)d_in[2];
    const float* gq    = (const float*)d_in[3];
    const float* betaq = (const float*)d_in[4];
    const float* mq    = (const float*)d_in[5];
    const float* vq    = (const float*)d_in[6];
    const float* Wk    = (const float*)d_in[7];
    const float* bk    = (const float*)d_in[8];
    const float* gk    = (const float*)d_in[9];
    const float* betak = (const float*)d_in[10];
    const float* mk    = (const float*)d_in[11];
    const float* vk    = (const float*)d_in[12];
    const float* Wv    = (const float*)d_in[13];
    const float* bv    = (const float*)d_in[14];
    const float* gamma = (const float*)d_in[15];
    float* out = (float*)d_out;

    // unconditional, idempotent; host-side attribute set (not a stream op)
    cudaFuncSetAttribute(fused_kernel, cudaFuncAttributeMaxDynamicSharedMemorySize, FK_SMEM);

    float* pd;
    cudaGetSymbolAddress((void**)&pd, g_pd);

    prep_kernel<<<BHW / 4, 256>>>(x, Wq, bq, gq, betaq, mq, vq,
                                  Wk, bk, gk, betak, mk, vk, Wv, bv);
    stats_kernel<<<dim3(NMT, B_, MZ_), 256>>>();
    scalev_kernel<<<(unsigned)(((size_t)B_ * C_ * HW_) / 256), 256>>>(gamma);
    fused_kernel<<<dim3(HW_ / 64, B_, NH_), 128, FK_SMEM>>>(pd);
    combine_kernel<<<(unsigned)(((size_t)BHW * C_) / 1024), 256>>>(x, out);
}

// round 14
// speedup vs baseline: 1.1223x; 1.1223x over previous
#include <cuda_runtime.h>
#include <cuda_bf16.h>
#include <cstdint>

#define EPS_ 1e-3f
#define LOG2E 1.4426950408889634f
#define B_   2
#define H_   96
#define W_   96
#define C_   64
#define CQ   8
#define HW_  9216
#define BHW  (B_*HW_)
#define NMT  72            // number of 128-wide n-chunks
#define MZ_  12            // m-splits in stats
#define MCH  (NMT / MZ_)   // chunks of 128 m per stats block

// ---------------- scratch (static device arrays; no allocation) ----------------
__device__ unsigned       g_q[BHW * CQ];                // Q' = tf32(q * log2e) bits [n][8]
__device__ unsigned       g_k[BHW * CQ];                // K  = tf32(k) bits [m][8]
__device__ float          g_v[BHW * C_];                // V rows, fp32 [n][c]
__device__ __nv_bfloat16  g_vsT[(size_t)B_ * C_ * HW_]; // Vs^T [b][c][n], bf16
__device__ float          g_part[B_ * MZ_ * HW_];       // stats partials [b][mz][n]

// ---------------- helpers ----------------
__device__ __forceinline__ unsigned f2tf32(float f) {
    unsigned r;
    asm("cvt.rna.tf32.f32 %0, %1;" : "=r"(r) : "f"(f));
    return r;
}
__device__ __forceinline__ float ex2(float x) {
    float r;
    asm("ex2.approx.f32 %0, %1;" : "=f"(r) : "f"(x));
    return r;
}
__device__ __forceinline__ unsigned packbf2(float hi, float lo) {
    unsigned r;
    asm("cvt.rn.bf16x2.f32 %0, %1, %2;" : "=r"(r) : "f"(hi), "f"(lo));
    return r;
}
__device__ __forceinline__ void mma_tf32(float* d, const unsigned* a, unsigned b0, unsigned b1) {
    asm volatile(
        "mma.sync.aligned.m16n8k8.row.col.f32.tf32.tf32.f32 "
        "{%0,%1,%2,%3}, {%4,%5,%6,%7}, {%8,%9}, {%0,%1,%2,%3};\n"
        : "+f"(d[0]), "+f"(d[1]), "+f"(d[2]), "+f"(d[3])
        : "r"(a[0]), "r"(a[1]), "r"(a[2]), "r"(a[3]), "r"(b0), "r"(b1));
}
__device__ __forceinline__ void mma_bf16(float* d, const unsigned* a, unsigned b0, unsigned b1) {
    asm volatile(
        "mma.sync.aligned.m16n8k16.row.col.f32.bf16.bf16.f32 "
        "{%0,%1,%2,%3}, {%4,%5,%6,%7}, {%8,%9}, {%0,%1,%2,%3};\n"
        : "+f"(d[0]), "+f"(d[1]), "+f"(d[2]), "+f"(d[3])
        : "r"(a[0]), "r"(a[1]), "r"(a[2]), "r"(a[3]), "r"(b0), "r"(b1));
}
__device__ __forceinline__ void ldsm4(unsigned* r, const void* p) {
    unsigned a = (unsigned)__cvta_generic_to_shared(p);
    asm volatile("ldmatrix.sync.aligned.m8n8.x4.shared.b16 {%0,%1,%2,%3}, [%4];"
                 : "=r"(r[0]), "=r"(r[1]), "=r"(r[2]), "=r"(r[3]) : "r"(a));
}
__device__ __forceinline__ void cpa16(void* dst, const void* src) {
    unsigned d = (unsigned)__cvta_generic_to_shared(dst);
    asm volatile("cp.async.cg.shared.global [%0], [%1], 16;" :: "r"(d), "l"(src));
}
__device__ __forceinline__ void cpa_commit() { asm volatile("cp.async.commit_group;"); }
template <int N>
__device__ __forceinline__ void cpa_wait() { asm volatile("cp.async.wait_group %0;" :: "n"(N)); }

// ---------------- kernel 1: fused convs + BN + ReLU (4 pixels / block) ----------------
__global__ __launch_bounds__(256) void prep_kernel(const float* __restrict__ x,
    const float* __restrict__ Wq, const float* __restrict__ bq,
    const float* __restrict__ gq, const float* __restrict__ betaq,
    const float* __restrict__ mq, const float* __restrict__ vq,
    const float* __restrict__ Wk, const float* __restrict__ bk,
    const float* __restrict__ gk, const float* __restrict__ betak,
    const float* __restrict__ mk, const float* __restrict__ vk,
    const float* __restrict__ Wv, const float* __restrict__ bv)
{
    __shared__ float xc[6][C_];
    __shared__ float xu[4][C_];
    __shared__ float xd[4][C_];
    int pix0 = blockIdx.x * 4;
    int b = pix0 / HW_;
    int n0 = pix0 - b * HW_;
    int h = n0 / W_, w0 = n0 - h * W_;
    int t = threadIdx.x;
    const float* xb = x + (size_t)b * HW_ * C_;

    for (int i = t; i < 6 * C_; i += 256) {
        int j = i >> 6, c = i & 63, wi = w0 - 1 + j;
        xc[j][c] = (wi >= 0 && wi < W_) ? xb[(h * W_ + wi) * C_ + c] : 0.f;
    }
    for (int i = t; i < 4 * C_; i += 256) {
        int j = i >> 6, c = i & 63;
        xu[j][c] = (h > 0)      ? xb[((h - 1) * W_ + w0 + j) * C_ + c] : 0.f;
        xd[j][c] = (h < H_ - 1) ? xb[((h + 1) * W_ + w0 + j) * C_ + c] : 0.f;
    }
    __syncthreads();

    int px = t >> 6, c = t & 63;
    int pix = pix0 + px;

    float acc = bv[c];
    #pragma unroll 8
    for (int ci = 0; ci < C_; ci++)
        acc = fmaf(xc[px + 1][ci], Wv[ci * C_ + c], acc);
    g_v[(size_t)pix * C_ + c] = acc;

    if (c < CQ) {
        float s = 0.f;
        #pragma unroll 8
        for (int ci = 0; ci < C_; ci++) {
            s = fmaf(xc[px    ][ci], Wq[(0 * C_ + ci) * CQ + c], s);
            s = fmaf(xc[px + 1][ci], Wq[(1 * C_ + ci) * CQ + c], s);
            s = fmaf(xc[px + 2][ci], Wq[(2 * C_ + ci) * CQ + c], s);
        }
        float sc  = gq[c] * rsqrtf(vq[c] + EPS_);
        float val = fmaf(s + bq[c] - mq[c], sc, betaq[c]);
        g_q[pix * CQ + c] = f2tf32(fmaxf(val, 0.f) * LOG2E);
    } else if (c < 2 * CQ) {
        int cc = c - CQ;
        float s = 0.f;
        #pragma unroll 8
        for (int ci = 0; ci < C_; ci++) {
            s = fmaf(xu[px    ][ci], Wk[(0 * C_ + ci) * CQ + cc], s);
            s = fmaf(xc[px + 1][ci], Wk[(1 * C_ + ci) * CQ + cc], s);
            s = fmaf(xd[px    ][ci], Wk[(2 * C_ + ci) * CQ + cc], s);
        }
        float sc  = gk[cc] * rsqrtf(vk[cc] + EPS_);
        float val = fmaf(s + bk[cc] - mk[cc], sc, betak[cc]);
        g_k[pix * CQ + cc] = f2tf32(fmaxf(val, 0.f));
    }
}

// ---------------- kernel 2: softmax-denominator partials ----------------
__global__ __launch_bounds__(256) void stats_kernel()
{
    __shared__ unsigned ks[2][128][12];
    int b  = blockIdx.y;
    int n0 = blockIdx.x * 128;
    int mz = blockIdx.z;
    int m_base = mz * (HW_ / MZ_);
    int t = threadIdx.x, lane = t & 31, w = t >> 5;
    int g = lane >> 2, tq = lane & 3;
    size_t bHW = (size_t)b * HW_;
    const unsigned* kb = &g_k[bHW * 8];

    unsigned bq[4];
    {
        const unsigned* qp = &g_q[(bHW + n0 + 16 * w + g) * 8];
        bq[0] = qp[tq];
        bq[1] = qp[tq + 4];
        bq[2] = qp[64 + tq];
        bq[3] = qp[64 + tq + 4];
    }

    {
        int row = t >> 1, seg = t & 1;
        cpa16(&ks[0][row][seg * 4], kb + (m_base + row) * 8 + seg * 4);
        cpa_commit();
    }

    float cs0 = 0.f, cs1 = 0.f, cs2 = 0.f, cs3 = 0.f;

    for (int ch = 0; ch < MCH; ch++) {
        int buf = ch & 1;
        if (ch + 1 < MCH) {
            int row = t >> 1, seg = t & 1;
            cpa16(&ks[buf ^ 1][row][seg * 4], kb + (m_base + (ch + 1) * 128 + row) * 8 + seg * 4);
            cpa_commit();
            cpa_wait<1>();
        } else {
            cpa_wait<0>();
        }
        __syncthreads();

        #pragma unroll
        for (int i = 0; i < 8; i++) {
            unsigned a[4];
            a[0] = ks[buf][16 * i + g    ][tq    ];
            a[1] = ks[buf][16 * i + g + 8][tq    ];
            a[2] = ks[buf][16 * i + g    ][tq + 4];
            a[3] = ks[buf][16 * i + g + 8][tq + 4];
            float d[4] = {0.f, 0.f, 0.f, 0.f};
            float e[4] = {0.f, 0.f, 0.f, 0.f};
            mma_tf32(d, a, bq[0], bq[1]);
            mma_tf32(e, a, bq[2], bq[3]);
            cs0 += ex2(d[0]) + ex2(d[2]);
            cs1 += ex2(d[1]) + ex2(d[3]);
            cs2 += ex2(e[0]) + ex2(e[2]);
            cs3 += ex2(e[1]) + ex2(e[3]);
        }
        __syncthreads();
    }

    #pragma unroll
    for (int s = 16; s >= 4; s >>= 1) {
        cs0 += __shfl_xor_sync(0xffffffffu, cs0, s);
        cs1 += __shfl_xor_sync(0xffffffffu, cs1, s);
        cs2 += __shfl_xor_sync(0xffffffffu, cs2, s);
        cs3 += __shfl_xor_sync(0xffffffffu, cs3, s);
    }
    if (lane < 4) {
        float* rp = &g_part[((b * MZ_) + mz) * HW_ + n0 + 16 * w];
        rp[2 * tq]     = cs0;
        rp[2 * tq + 1] = cs1;
        rp[2 * tq + 8] = cs2;
        rp[2 * tq + 9] = cs3;
    }
}

// ---------------- kernel 3: Vs^T = bf16(gamma * v / rowsum), rowsum reduced inline ----------------
__global__ void scalev_kernel(const float* __restrict__ gamma)
{
    size_t o = (size_t)blockIdx.x * 256 + threadIdx.x;  // over B*C*HW, n fastest
    int n = (int)(o % HW_);
    int c = (int)((o / HW_) % C_);
    int b = (int)(o / ((size_t)HW_ * C_));
    float s = 0.f;
    #pragma unroll
    for (int mz = 0; mz < MZ_; mz++)
        s += g_part[((b * MZ_) + mz) * HW_ + n];
    float val = g_v[((size_t)(b * HW_ + n)) * C_ + c] * gamma[0] / s;
    g_vsT[o] = __float2bfloat16(val);
}

// ---------------- kernel 4: fused P-in-registers GEMM + residual ----------------
// block = 64 m x 64 c, 128 threads (4 warps). Warp owns 32 m (wm=w&1) and every
// other n-chunk (wn=w>>1). Inner loop is a distance-2 software pipeline:
//   A: tf32 MMA for step s+2,  B: ex2/pack for step s+1,  C: ldsm+bf16 MMA for s
// so MUFU of s+1 overlaps tensor issue of s within the warp.
#define VSOFF   0
#define VSBUF   17408                    // 64 rows x 136 bf16
#define QSOFF   (4 * VSBUF)              // 69632
#define QSBUF   4096                     // 128 rows x 8 words
#define FK_SMEM (QSOFF + 4 * QSBUF)      // 86016

__global__ __launch_bounds__(128, 2)
void fused_kernel(const float* __restrict__ x, float* __restrict__ out)
{
    extern __shared__ __align__(16) char smem[];
    __nv_bfloat16* VsB = (__nv_bfloat16*)(smem + VSOFF);
    unsigned*      QsB = (unsigned*)(smem + QSOFF);
#define VS(bf, p, r, c) VsB[((bf) * 2 + (p)) * (64 * 136) + (r) * 136 + (c)]
#define QS(bf, p)       (QsB + ((bf) * 2 + (p)) * 1024)

    int b  = blockIdx.y;
    int m0 = blockIdx.x * 64;
    int t = threadIdx.x, lane = t & 31, w = t >> 5;     // 4 warps
    int g = lane >> 2, tq = lane & 3;
    int wm = w & 1;        // m-half (32 rows)
    int wn = w >> 1;       // n-chunk parity
    size_t bHW = (size_t)b * HW_;
    const unsigned* kb = &g_k[bHW * 8];
    const unsigned* qb = &g_q[bHW * 8];
    const __nv_bfloat16* Ag = &g_vsT[(size_t)b * C_ * HW_];

    // K A-fragments for this warp's 32 m-rows (2 m-tiles, fixed all kernel)
    int mw = m0 + 32 * wm;
    unsigned ka[2][4];
    #pragma unroll
    for (int mt = 0; mt < 2; mt++) {
        ka[mt][0] = kb[(mw + 16 * mt + g    ) * 8 + tq    ];
        ka[mt][1] = kb[(mw + 16 * mt + g + 8) * 8 + tq    ];
        ka[mt][2] = kb[(mw + 16 * mt + g    ) * 8 + tq + 4];
        ka[mt][3] = kb[(mw + 16 * mt + g + 8) * 8 + tq + 4];
    }

    float acc[2][8][4];
    #pragma unroll
    for (int mt = 0; mt < 2; mt++)
        #pragma unroll
        for (int i = 0; i < 8; i++)
            #pragma unroll
            for (int j = 0; j < 4; j++) acc[mt][i][j] = 0.f;

    // prefetch pair 0 (chunks 0 and 1)
    #pragma unroll
    for (int p = 0; p < 2; p++) {
        #pragma unroll
        for (int j = 0; j < 8; j++) {
            int idx = t + j * 128, row = idx >> 4, seg = idx & 15;
            cpa16(&VS(0, p, row, seg * 8), Ag + (size_t)row * HW_ + p * 128 + seg * 8);
        }
        #pragma unroll
        for (int j = 0; j < 2; j++) {
            int idx = t + j * 128, row = idx >> 1, seg = idx & 1;
            cpa16(QS(0, p) + row * 8 + seg * 4, qb + (size_t)(p * 128 + row) * 8 + seg * 4);
        }
    }
    cpa_commit();
    cpa_wait<0>();
    __syncthreads();

    for (int jp = 0; jp < NMT / 2; jp++) {
        int buf = jp & 1;
        bool more = (jp + 1 < NMT / 2);
        if (more) {
            int nbase = (jp + 1) * 256;
            #pragma unroll
            for (int p = 0; p < 2; p++) {
                #pragma unroll
                for (int j = 0; j < 8; j++) {
                    int idx = t + j * 128, row = idx >> 4, seg = idx & 15;
                    cpa16(&VS(buf ^ 1, p, row, seg * 8),
                          Ag + (size_t)row * HW_ + nbase + p * 128 + seg * 8);
                }
                #pragma unroll
                for (int j = 0; j < 2; j++) {
                    int idx = t + j * 128, row = idx >> 1, seg = idx & 1;
                    cpa16(QS(buf ^ 1, p) + row * 8 + seg * 4,
                          qb + (size_t)(nbase + p * 128 + row) * 8 + seg * 4);
                }
            }
            cpa_commit();
        }

        // consume chunk 2*jp + wn with a distance-2 software pipeline
        const unsigned* qs = QS(buf, wn);
        float dp[2][2][8];       // [pipe slot][mt][d0..3,e0..3]
        unsigned af[2][4];       // A-frags for current step

        // pipeline prologue: tf32 for steps 0,1; ex2/pack for step 0
        #pragma unroll
        for (int pi = 0; pi < 2; pi++) {
            int nb = 16 * pi;
            unsigned q0 = qs[(nb + g    ) * 8 + tq    ];
            unsigned q1 = qs[(nb + g    ) * 8 + tq + 4];
            unsigned q2 = qs[(nb + 8 + g) * 8 + tq    ];
            unsigned q3 = qs[(nb + 8 + g) * 8 + tq + 4];
            #pragma unroll
            for (int mt = 0; mt < 2; mt++) {
                float* dd = dp[pi][mt];
                #pragma unroll
                for (int j = 0; j < 8; j++) dd[j] = 0.f;
                mma_tf32(dd,     ka[mt], q0, q1);
                mma_tf32(dd + 4, ka[mt], q2, q3);
            }
        }
        #pragma unroll
        for (int mt = 0; mt < 2; mt++) {
            af[mt][0] = packbf2(ex2(dp[0][mt][1]), ex2(dp[0][mt][0]));
            af[mt][1] = packbf2(ex2(dp[0][mt][3]), ex2(dp[0][mt][2]));
            af[mt][2] = packbf2(ex2(dp[0][mt][5]), ex2(dp[0][mt][4]));
            af[mt][3] = packbf2(ex2(dp[0][mt][7]), ex2(dp[0][mt][6]));
        }

        #pragma unroll
        for (int s = 0; s < 8; s++) {
            // A: tf32 MMA for step s+2 into the slot freed by step s
            if (s + 2 < 8) {
                int nb = 16 * (s + 2);
                unsigned q0 = qs[(nb + g    ) * 8 + tq    ];
                unsigned q1 = qs[(nb + g    ) * 8 + tq + 4];
                unsigned q2 = qs[(nb + 8 + g) * 8 + tq    ];
                unsigned q3 = qs[(nb + 8 + g) * 8 + tq + 4];
                #pragma unroll
                for (int mt = 0; mt < 2; mt++) {
                    float* dd = dp[s & 1][mt];
                    #pragma unroll
                    for (int j = 0; j < 8; j++) dd[j] = 0.f;
                    mma_tf32(dd,     ka[mt], q0, q1);
                    mma_tf32(dd + 4, ka[mt], q2, q3);
                }
            }
            // B: ex2/pack for step s+1 (independent of C below)
            unsigned afn[2][4];
            if (s + 1 < 8) {
                #pragma unroll
                for (int mt = 0; mt < 2; mt++) {
                    const float* dd = dp[(s + 1) & 1][mt];
                    afn[mt][0] = packbf2(ex2(dd[1]), ex2(dd[0]));
                    afn[mt][1] = packbf2(ex2(dd[3]), ex2(dd[2]));
                    afn[mt][2] = packbf2(ex2(dd[5]), ex2(dd[4]));
                    afn[mt][3] = packbf2(ex2(dd[7]), ex2(dd[6]));
                }
            }
            // C: consume step s (tensor)
            {
                int nb = 16 * s;
                #pragma unroll
                for (int cb = 0; cb < 4; cb++) {
                    unsigned bb[4];
                    ldsm4(bb, &VS(buf, wn, cb * 16 + (lane & 7) + ((lane >> 4) & 1) * 8,
                                  nb + ((lane >> 3) & 1) * 8));
                    #pragma unroll
                    for (int mt = 0; mt < 2; mt++) {
                        mma_bf16(acc[mt][2 * cb    ], af[mt], bb[0], bb[1]);
                        mma_bf16(acc[mt][2 * cb + 1], af[mt], bb[2], bb[3]);
                    }
                }
            }
            // rotate
            if (s + 1 < 8) {
                #pragma unroll
                for (int mt = 0; mt < 2; mt++)
                    #pragma unroll
                    for (int j = 0; j < 4; j++) af[mt][j] = afn[mt][j];
            }
        }
        if (more) cpa_wait<0>();
        __syncthreads();
    }

    // cross-parity reduction (reuse Vs smem area; conflict-free [idx][lane] layout)
    float* red = (float*)smem;
    if (wn == 1) {
        const float* afl = (const float*)acc;
        #pragma unroll
        for (int i = 0; i < 64; i++) red[(wm * 64 + i) * 32 + lane] = afl[i];
    }
    __syncthreads();
    if (wn == 0) {
        float* afl = (float*)acc;
        #pragma unroll
        for (int i = 0; i < 64; i++) afl[i] += red[(wm * 64 + i) * 32 + lane];

        // epilogue: out[b][m][c] = D[m][c] + x[b][m][c], 32 rows per warp
        #pragma unroll
        for (int mt = 0; mt < 2; mt++) {
            int m = m0 + 32 * wm + 16 * mt + g;
            #pragma unroll
            for (int o = 0; o < 8; o++) {
                int c = 8 * o + 2 * tq;
                size_t i0 = (bHW + m) * (size_t)C_ + c;
                size_t i1 = i0 + 8 * C_;
                float2 x0 = *(const float2*)&x[i0];
                float2 x1 = *(const float2*)&x[i1];
                float2 o0 = { acc[mt][o][0] + x0.x, acc[mt][o][1] + x0.y };
                float2 o1 = { acc[mt][o][2] + x1.x, acc[mt][o][3] + x1.y };
                *(float2*)&out[i0] = o0;
                *(float2*)&out[i1] = o1;
            }
        }
    }
#undef VS
#undef QS
}

// ---------------- launch ----------------
extern "C" void kernel_launch(void* const* d_in, const int* in_sizes, int n_in,
                              void* d_out, int out_size)
{
    const float* x     = (const float*)d_in[0];
    const float* Wq    = (const float*)d_in[1];
    const float* bq    = (const float*)d_in[2];
    const float* gq    = (const float*)d_in[3];
    const float* betaq = (const float*)d_in[4];
    const float* mq    = (const float*)d_in[5];
    const float* vq    = (const float*)d_in[6];
    const float* Wk    = (const float*)d_in[7];
    const float* bk    = (const float*)d_in[8];
    const float* gk    = (const float*)d_in[9];
    const float* betak = (const float*)d_in[10];
    const float* mk    = (const float*)d_in[11];
    const float* vk    = (const float*)d_in[12];
    const float* Wv    = (const float*)d_in[13];
    const float* bv    = (const float*)d_in[14];
    const float* gamma = (const float*)d_in[15];
    float* out = (float*)d_out;

    // unconditional, idempotent; host-side attribute set (not a stream op)
    cudaFuncSetAttribute(fused_kernel, cudaFuncAttributeMaxDynamicSharedMemorySize, FK_SMEM);

    prep_kernel<<<BHW / 4, 256>>>(x, Wq, bq, gq, betaq, mq, vq,
                                  Wk, bk, gk, betak, mk, vk, Wv, bv);
    stats_kernel<<<dim3(NMT, B_, MZ_), 256>>>();
    scalev_kernel<<<(unsigned)(((size_t)B_ * C_ * HW_) / 256), 256>>>(gamma);
    fused_kernel<<<dim3(HW_ / 64, B_), 128, FK_SMEM>>>(x, out);
}

// round 15
// speedup vs baseline: 1.1369x; 1.0130x over previous
#include <cuda_runtime.h>
#include <cuda_bf16.h>
#include <cstdint>

#define EPS_ 1e-3f
#define LOG2E 1.4426950408889634f
#define B_   2
#define H_   96
#define W_   96
#define C_   64
#define CQ   8
#define HW_  9216
#define BHW  (B_*HW_)
#define NMT  72            // number of 128-wide n-chunks
#define MZ_  8             // m-splits in stats
#define MCH  (NMT / MZ_)   // chunks of 128 m per stats block

// Schraudolph-in-bf16: for x >= 0, bits(x + 2^15) = 0x47000000 + round(x*256).
// bf16(2^x) bits ~= round(x*128) + (127<<7) - 7  =>  (bits>>1) + 0xDC803F79 (wraps).
#define KEXP_ 0xDC803F79u

// ---------------- scratch (static device arrays; no allocation) ----------------
__device__ unsigned       g_q[BHW * CQ];                // Q' = tf32(q * log2e) bits [n][8]
__device__ unsigned       g_k[BHW * CQ];                // K  = tf32(k) bits [m][8]
__device__ float          g_v[BHW * C_];                // V rows, fp32 [n][c]
__device__ __nv_bfloat16  g_vsT[(size_t)B_ * C_ * HW_]; // Vs^T [b][c][n], bf16
__device__ float          g_part[B_ * MZ_ * HW_];       // stats partials [b][mz][n]

// ---------------- helpers ----------------
__device__ __forceinline__ unsigned f2tf32(float f) {
    unsigned r;
    asm("cvt.rna.tf32.f32 %0, %1;" : "=r"(r) : "f"(f));
    return r;
}
// bf16x2 of (2^lo, 2^hi) via integer Schraudolph — no MUFU, no CVT
__device__ __forceinline__ unsigned fexp2pack(float lo, float hi) {
    unsigned blo = (__float_as_uint(lo + 32768.0f) >> 1) + KEXP_;
    unsigned bhi = (__float_as_uint(hi + 32768.0f) >> 1) + KEXP_;
    return blo | (bhi << 16);
}
// fp32 of 2^x with the SAME bf16 quantization (stats must match fused)
__device__ __forceinline__ float fexp2(float x) {
    unsigned b = (__float_as_uint(x + 32768.0f) >> 1) + KEXP_;
    return __int_as_float((int)(b << 16));
}
__device__ __forceinline__ void mma_tf32(float* d, const unsigned* a, unsigned b0, unsigned b1) {
    asm volatile(
        "mma.sync.aligned.m16n8k8.row.col.f32.tf32.tf32.f32 "
        "{%0,%1,%2,%3}, {%4,%5,%6,%7}, {%8,%9}, {%0,%1,%2,%3};\n"
        : "+f"(d[0]), "+f"(d[1]), "+f"(d[2]), "+f"(d[3])
        : "r"(a[0]), "r"(a[1]), "r"(a[2]), "r"(a[3]), "r"(b0), "r"(b1));
}
__device__ __forceinline__ void mma_bf16(float* d, const unsigned* a, unsigned b0, unsigned b1) {
    asm volatile(
        "mma.sync.aligned.m16n8k16.row.col.f32.bf16.bf16.f32 "
        "{%0,%1,%2,%3}, {%4,%5,%6,%7}, {%8,%9}, {%0,%1,%2,%3};\n"
        : "+f"(d[0]), "+f"(d[1]), "+f"(d[2]), "+f"(d[3])
        : "r"(a[0]), "r"(a[1]), "r"(a[2]), "r"(a[3]), "r"(b0), "r"(b1));
}
__device__ __forceinline__ void ldsm4(unsigned* r, const void* p) {
    unsigned a = (unsigned)__cvta_generic_to_shared(p);
    asm volatile("ldmatrix.sync.aligned.m8n8.x4.shared.b16 {%0,%1,%2,%3}, [%4];"
                 : "=r"(r[0]), "=r"(r[1]), "=r"(r[2]), "=r"(r[3]) : "r"(a));
}
__device__ __forceinline__ void cpa16(void* dst, const void* src) {
    unsigned d = (unsigned)__cvta_generic_to_shared(dst);
    asm volatile("cp.async.cg.shared.global [%0], [%1], 16;" :: "r"(d), "l"(src));
}
__device__ __forceinline__ void cpa_commit() { asm volatile("cp.async.commit_group;"); }
template <int N>
__device__ __forceinline__ void cpa_wait() { asm volatile("cp.async.wait_group %0;" :: "n"(N)); }

// ---------------- kernel 1: fused convs + BN + ReLU (4 pixels / block) ----------------
__global__ __launch_bounds__(256) void prep_kernel(const float* __restrict__ x,
    const float* __restrict__ Wq, const float* __restrict__ bq,
    const float* __restrict__ gq, const float* __restrict__ betaq,
    const float* __restrict__ mq, const float* __restrict__ vq,
    const float* __restrict__ Wk, const float* __restrict__ bk,
    const float* __restrict__ gk, const float* __restrict__ betak,
    const float* __restrict__ mk, const float* __restrict__ vk,
    const float* __restrict__ Wv, const float* __restrict__ bv)
{
    __shared__ float xc[6][C_];
    __shared__ float xu[4][C_];
    __shared__ float xd[4][C_];
    int pix0 = blockIdx.x * 4;
    int b = pix0 / HW_;
    int n0 = pix0 - b * HW_;
    int h = n0 / W_, w0 = n0 - h * W_;
    int t = threadIdx.x;
    const float* xb = x + (size_t)b * HW_ * C_;

    for (int i = t; i < 6 * C_; i += 256) {
        int j = i >> 6, c = i & 63, wi = w0 - 1 + j;
        xc[j][c] = (wi >= 0 && wi < W_) ? xb[(h * W_ + wi) * C_ + c] : 0.f;
    }
    for (int i = t; i < 4 * C_; i += 256) {
        int j = i >> 6, c = i & 63;
        xu[j][c] = (h > 0)      ? xb[((h - 1) * W_ + w0 + j) * C_ + c] : 0.f;
        xd[j][c] = (h < H_ - 1) ? xb[((h + 1) * W_ + w0 + j) * C_ + c] : 0.f;
    }
    __syncthreads();

    int px = t >> 6, c = t & 63;
    int pix = pix0 + px;

    float acc = bv[c];
    #pragma unroll 8
    for (int ci = 0; ci < C_; ci++)
        acc = fmaf(xc[px + 1][ci], Wv[ci * C_ + c], acc);
    g_v[(size_t)pix * C_ + c] = acc;

    if (c < CQ) {
        float s = 0.f;
        #pragma unroll 8
        for (int ci = 0; ci < C_; ci++) {
            s = fmaf(xc[px    ][ci], Wq[(0 * C_ + ci) * CQ + c], s);
            s = fmaf(xc[px + 1][ci], Wq[(1 * C_ + ci) * CQ + c], s);
            s = fmaf(xc[px + 2][ci], Wq[(2 * C_ + ci) * CQ + c], s);
        }
        float sc  = gq[c] * rsqrtf(vq[c] + EPS_);
        float val = fmaf(s + bq[c] - mq[c], sc, betaq[c]);
        g_q[pix * CQ + c] = f2tf32(fmaxf(val, 0.f) * LOG2E);
    } else if (c < 2 * CQ) {
        int cc = c - CQ;
        float s = 0.f;
        #pragma unroll 8
        for (int ci = 0; ci < C_; ci++) {
            s = fmaf(xu[px    ][ci], Wk[(0 * C_ + ci) * CQ + cc], s);
            s = fmaf(xc[px + 1][ci], Wk[(1 * C_ + ci) * CQ + cc], s);
            s = fmaf(xd[px    ][ci], Wk[(2 * C_ + ci) * CQ + cc], s);
        }
        float sc  = gk[cc] * rsqrtf(vk[cc] + EPS_);
        float val = fmaf(s + bk[cc] - mk[cc], sc, betak[cc]);
        g_k[pix * CQ + cc] = f2tf32(fmaxf(val, 0.f));
    }
}

// ---------------- kernel 2: softmax-denominator partials ----------------
__global__ __launch_bounds__(256) void stats_kernel()
{
    __shared__ unsigned ks[2][128][12];
    int b  = blockIdx.y;
    int n0 = blockIdx.x * 128;
    int mz = blockIdx.z;
    int m_base = mz * (HW_ / MZ_);
    int t = threadIdx.x, lane = t & 31, w = t >> 5;
    int g = lane >> 2, tq = lane & 3;
    size_t bHW = (size_t)b * HW_;
    const unsigned* kb = &g_k[bHW * 8];

    unsigned bq[4];
    {
        const unsigned* qp = &g_q[(bHW + n0 + 16 * w + g) * 8];
        bq[0] = qp[tq];
        bq[1] = qp[tq + 4];
        bq[2] = qp[64 + tq];
        bq[3] = qp[64 + tq + 4];
    }

    {
        int row = t >> 1, seg = t & 1;
        cpa16(&ks[0][row][seg * 4], kb + (m_base + row) * 8 + seg * 4);
        cpa_commit();
    }

    float cs0 = 0.f, cs1 = 0.f, cs2 = 0.f, cs3 = 0.f;

    for (int ch = 0; ch < MCH; ch++) {
        int buf = ch & 1;
        if (ch + 1 < MCH) {
            int row = t >> 1, seg = t & 1;
            cpa16(&ks[buf ^ 1][row][seg * 4], kb + (m_base + (ch + 1) * 128 + row) * 8 + seg * 4);
            cpa_commit();
            cpa_wait<1>();
        } else {
            cpa_wait<0>();
        }
        __syncthreads();

        #pragma unroll
        for (int i = 0; i < 8; i++) {
            unsigned a[4];
            a[0] = ks[buf][16 * i + g    ][tq    ];
            a[1] = ks[buf][16 * i + g + 8][tq    ];
            a[2] = ks[buf][16 * i + g    ][tq + 4];
            a[3] = ks[buf][16 * i + g + 8][tq + 4];
            float d[4] = {0.f, 0.f, 0.f, 0.f};
            float e[4] = {0.f, 0.f, 0.f, 0.f};
            mma_tf32(d, a, bq[0], bq[1]);
            mma_tf32(e, a, bq[2], bq[3]);
            cs0 += fexp2(d[0]) + fexp2(d[2]);
            cs1 += fexp2(d[1]) + fexp2(d[3]);
            cs2 += fexp2(e[0]) + fexp2(e[2]);
            cs3 += fexp2(e[1]) + fexp2(e[3]);
        }
        __syncthreads();
    }

    #pragma unroll
    for (int s = 16; s >= 4; s >>= 1) {
        cs0 += __shfl_xor_sync(0xffffffffu, cs0, s);
        cs1 += __shfl_xor_sync(0xffffffffu, cs1, s);
        cs2 += __shfl_xor_sync(0xffffffffu, cs2, s);
        cs3 += __shfl_xor_sync(0xffffffffu, cs3, s);
    }
    if (lane < 4) {
        float* rp = &g_part[((b * MZ_) + mz) * HW_ + n0 + 16 * w];
        rp[2 * tq]     = cs0;
        rp[2 * tq + 1] = cs1;
        rp[2 * tq + 8] = cs2;
        rp[2 * tq + 9] = cs3;
    }
}

// ---------------- kernel 3: Vs^T = bf16(gamma * v / rowsum), rowsum reduced inline ----------------
__global__ void scalev_kernel(const float* __restrict__ gamma)
{
    size_t o = (size_t)blockIdx.x * 256 + threadIdx.x;  // over B*C*HW, n fastest
    int n = (int)(o % HW_);
    int c = (int)((o / HW_) % C_);
    int b = (int)(o / ((size_t)HW_ * C_));
    float s = 0.f;
    #pragma unroll
    for (int mz = 0; mz < MZ_; mz++)
        s += g_part[((b * MZ_) + mz) * HW_ + n];
    float val = g_v[((size_t)(b * HW_ + n)) * C_ + c] * gamma[0] / s;
    g_vsT[o] = __float2bfloat16(val);
}

// ---------------- kernel 4: fused P-in-registers GEMM + residual ----------------
// block = 64 m x 64 c, 128 threads (4 warps). Warp owns 32 m (wm=w&1) and every
// other n-chunk (wn=w>>1). P built via integer Schraudolph (no MUFU/CVT).
#define VSOFF   0
#define VSBUF   17408                    // 64 rows x 136 bf16
#define QSOFF   (4 * VSBUF)              // 69632
#define QSBUF   4096                     // 128 rows x 8 words
#define FK_SMEM (QSOFF + 4 * QSBUF)      // 86016

__global__ __launch_bounds__(128, 2)
void fused_kernel(const float* __restrict__ x, float* __restrict__ out)
{
    extern __shared__ __align__(16) char smem[];
    __nv_bfloat16* VsB = (__nv_bfloat16*)(smem + VSOFF);
    unsigned*      QsB = (unsigned*)(smem + QSOFF);
#define VS(bf, p, r, c) VsB[((bf) * 2 + (p)) * (64 * 136) + (r) * 136 + (c)]
#define QS(bf, p)       (QsB + ((bf) * 2 + (p)) * 1024)

    int b  = blockIdx.y;
    int m0 = blockIdx.x * 64;
    int t = threadIdx.x, lane = t & 31, w = t >> 5;     // 4 warps
    int g = lane >> 2, tq = lane & 3;
    int wm = w & 1;        // m-half (32 rows)
    int wn = w >> 1;       // n-chunk parity
    size_t bHW = (size_t)b * HW_;
    const unsigned* kb = &g_k[bHW * 8];
    const unsigned* qb = &g_q[bHW * 8];
    const __nv_bfloat16* Ag = &g_vsT[(size_t)b * C_ * HW_];

    // K A-fragments for this warp's 32 m-rows (2 m-tiles, fixed all kernel)
    int mw = m0 + 32 * wm;
    unsigned ka[2][4];
    #pragma unroll
    for (int mt = 0; mt < 2; mt++) {
        ka[mt][0] = kb[(mw + 16 * mt + g    ) * 8 + tq    ];
        ka[mt][1] = kb[(mw + 16 * mt + g + 8) * 8 + tq    ];
        ka[mt][2] = kb[(mw + 16 * mt + g    ) * 8 + tq + 4];
        ka[mt][3] = kb[(mw + 16 * mt + g + 8) * 8 + tq + 4];
    }

    float acc[2][8][4];
    #pragma unroll
    for (int mt = 0; mt < 2; mt++)
        #pragma unroll
        for (int i = 0; i < 8; i++)
            #pragma unroll
            for (int j = 0; j < 4; j++) acc[mt][i][j] = 0.f;

    // prefetch pair 0 (chunks 0 and 1)
    #pragma unroll
    for (int p = 0; p < 2; p++) {
        #pragma unroll
        for (int j = 0; j < 8; j++) {
            int idx = t + j * 128, row = idx >> 4, seg = idx & 15;
            cpa16(&VS(0, p, row, seg * 8), Ag + (size_t)row * HW_ + p * 128 + seg * 8);
        }
        #pragma unroll
        for (int j = 0; j < 2; j++) {
            int idx = t + j * 128, row = idx >> 1, seg = idx & 1;
            cpa16(QS(0, p) + row * 8 + seg * 4, qb + (size_t)(p * 128 + row) * 8 + seg * 4);
        }
    }
    cpa_commit();
    cpa_wait<0>();
    __syncthreads();

    for (int jp = 0; jp < NMT / 2; jp++) {
        int buf = jp & 1;
        bool more = (jp + 1 < NMT / 2);
        if (more) {
            int nbase = (jp + 1) * 256;
            #pragma unroll
            for (int p = 0; p < 2; p++) {
                #pragma unroll
                for (int j = 0; j < 8; j++) {
                    int idx = t + j * 128, row = idx >> 4, seg = idx & 15;
                    cpa16(&VS(buf ^ 1, p, row, seg * 8),
                          Ag + (size_t)row * HW_ + nbase + p * 128 + seg * 8);
                }
                #pragma unroll
                for (int j = 0; j < 2; j++) {
                    int idx = t + j * 128, row = idx >> 1, seg = idx & 1;
                    cpa16(QS(buf ^ 1, p) + row * 8 + seg * 4,
                          qb + (size_t)(nbase + p * 128 + row) * 8 + seg * 4);
                }
            }
            cpa_commit();
        }

        // consume chunk 2*jp + wn
        const unsigned* qs = QS(buf, wn);
        #pragma unroll
        for (int s = 0; s < 8; s++) {
            int nb = 16 * s;
            unsigned q0 = qs[(nb + g    ) * 8 + tq    ];
            unsigned q1 = qs[(nb + g    ) * 8 + tq + 4];
            unsigned q2 = qs[(nb + 8 + g) * 8 + tq    ];
            unsigned q3 = qs[(nb + 8 + g) * 8 + tq + 4];
            unsigned a[2][4];
            #pragma unroll
            for (int mt = 0; mt < 2; mt++) {
                float d[4] = {0.f, 0.f, 0.f, 0.f};
                float e[4] = {0.f, 0.f, 0.f, 0.f};
                mma_tf32(d, ka[mt], q0, q1);
                mma_tf32(e, ka[mt], q2, q3);
                a[mt][0] = fexp2pack(d[0], d[1]);
                a[mt][1] = fexp2pack(d[2], d[3]);
                a[mt][2] = fexp2pack(e[0], e[1]);
                a[mt][3] = fexp2pack(e[2], e[3]);
            }
            #pragma unroll
            for (int cb = 0; cb < 4; cb++) {
                unsigned bb[4];
                ldsm4(bb, &VS(buf, wn, cb * 16 + (lane & 7) + ((lane >> 4) & 1) * 8,
                              nb + ((lane >> 3) & 1) * 8));
                #pragma unroll
                for (int mt = 0; mt < 2; mt++) {
                    mma_bf16(acc[mt][2 * cb    ], a[mt], bb[0], bb[1]);
                    mma_bf16(acc[mt][2 * cb + 1], a[mt], bb[2], bb[3]);
                }
            }
        }
        if (more) cpa_wait<0>();
        __syncthreads();
    }

    // cross-parity reduction (reuse Vs smem area; conflict-free [idx][lane] layout)
    float* red = (float*)smem;
    if (wn == 1) {
        const float* afl = (const float*)acc;
        #pragma unroll
        for (int i = 0; i < 64; i++) red[(wm * 64 + i) * 32 + lane] = afl[i];
    }
    __syncthreads();
    if (wn == 0) {
        float* afl = (float*)acc;
        #pragma unroll
        for (int i = 0; i < 64; i++) afl[i] += red[(wm * 64 + i) * 32 + lane];

        // epilogue: out[b][m][c] = D[m][c] + x[b][m][c], 32 rows per warp
        #pragma unroll
        for (int mt = 0; mt < 2; mt++) {
            int m = m0 + 32 * wm + 16 * mt + g;
            #pragma unroll
            for (int o = 0; o < 8; o++) {
                int c = 8 * o + 2 * tq;
                size_t i0 = (bHW + m) * (size_t)C_ + c;
                size_t i1 = i0 + 8 * C_;
                float2 x0 = *(const float2*)&x[i0];
                float2 x1 = *(const float2*)&x[i1];
                float2 o0 = { acc[mt][o][0] + x0.x, acc[mt][o][1] + x0.y };
                float2 o1 = { acc[mt][o][2] + x1.x, acc[mt][o][3] + x1.y };
                *(float2*)&out[i0] = o0;
                *(float2*)&out[i1] = o1;
            }
        }
    }
#undef VS
#undef QS
}

// ---------------- launch ----------------
extern "C" void kernel_launch(void* const* d_in, const int* in_sizes, int n_in,
                              void* d_out, int out_size)
{
    const float* x     = (const float*)d_in[0];
    const float* Wq    = (const float*)d_in[1];
    const float* bq    = (const float*)d_in[2];
    const float* gq    = (const float*)d_in[3];
    const float* betaq = (const float*)d_in[4];
    const float* mq    = (const float*)d_in[5];
    const float* vq    = (const float*)d_in[6];
    const float* Wk    = (const float*)d_in[7];
    const float* bk    = (const float*)d_in[8];
    const float* gk    = (const float*)d_in[9];
    const float* betak = (const float*)d_in[10];
    const float* mk    = (const float*)d_in[11];
    const float* vk    = (const float*)d_in[12];
    const float* Wv    = (const float*)d_in[13];
    const float* bv    = (const float*)d_in[14];
    const float* gamma = (const float*)d_in[15];
    float* out = (float*)d_out;

    // unconditional, idempotent; host-side attribute set (not a stream op)
    cudaFuncSetAttribute(fused_kernel, cudaFuncAttributeMaxDynamicSharedMemorySize, FK_SMEM);

    prep_kernel<<<BHW / 4, 256>>>(x, Wq, bq, gq, betaq, mq, vq,
                                  Wk, bk, gk, betak, mk, vk, Wv, bv);
    stats_kernel<<<dim3(NMT, B_, MZ_), 256>>>();
    scalev_kernel<<<(unsigned)(((size_t)B_ * C_ * HW_) / 256), 256>>>(gamma);
    fused_kernel<<<dim3(HW_ / 64, B_), 128, FK_SMEM>>>(x, out);
}